// round 15
// baseline (speedup 1.0000x reference)
#include <cuda_runtime.h>
#include <cuda_bf16.h>
#include <cuda_fp16.h>
#include <cstdint>

#define NN 20000
#define EE 640000
#define BBATCH 2
#define HH 128
#define OO 10
#define PAD 192
#define ROWS (BBATCH * NN)

// ---------------- scratch ----------------------------------------------------
__device__ int   g_fill[NN];          // degree counter / final degree
__device__ int   g_ell[NN * PAD];     // ELL adjacency (src ids)
__device__ float g_dinv[NN];
__device__ int   g_is64;
__device__ __align__(16) __half g_h16[ROWS * HH];   // fp16 gather table (gemm out)
__device__ __align__(16) float  g_buf1[ROWS * HH];  // fp32 post-agg
__device__ float g_bnsum1[HH], g_bnsq1[HH];   // layer-1 BN stats
__device__ float g_bnsum2[HH], g_bnsq2[HH];   // layer-2 BN stats
// W fragment packs (bf16 hi/lo, m16n8k16): 8 k-chunks x 1024 u32 (16nt x 32 x 2)
__device__ __align__(16) unsigned g_fW1hi[8192];
__device__ __align__(16) unsigned g_fW1lo[8192];
__device__ __align__(16) unsigned g_fW2hi[8192];
__device__ __align__(16) unsigned g_fW2lo[8192];
// Wc fragments: 8 k-chunks x 2 nt x 32 lanes x 2 regs = 1024 u32
__device__ __align__(16) unsigned g_fWchi[1024];
__device__ __align__(16) unsigned g_fWclo[1024];

// ---------------- helpers ----------------------------------------------------
__device__ __forceinline__ unsigned short bfbits(float x) {
    __nv_bfloat16 h = __float2bfloat16_rn(x);
    return *(unsigned short*)&h;
}
__device__ __forceinline__ float bffloat(unsigned short u) {
    __nv_bfloat16 h = *(__nv_bfloat16*)&u;
    return __bfloat162float(h);
}
// split (x,y) into packed bf16x2 hi and lo parts (lower 16 bits = x)
__device__ __forceinline__ void bfsplit2(float x, float y, unsigned& hi, unsigned& lo) {
    unsigned short hx = bfbits(x), hy = bfbits(y);
    unsigned short lx = bfbits(x - bffloat(hx));
    unsigned short ly = bfbits(y - bffloat(hy));
    hi = (unsigned)hx | ((unsigned)hy << 16);
    lo = (unsigned)lx | ((unsigned)ly << 16);
}

__device__ __forceinline__ void mma_bf16(float* d, unsigned a0, unsigned a1,
                                         unsigned a2, unsigned a3,
                                         unsigned b0, unsigned b1) {
    asm volatile(
        "mma.sync.aligned.m16n8k16.row.col.f32.bf16.bf16.f32 "
        "{%0,%1,%2,%3},{%4,%5,%6,%7},{%8,%9},{%0,%1,%2,%3};\n"
        : "+f"(d[0]), "+f"(d[1]), "+f"(d[2]), "+f"(d[3])
        : "r"(a0), "r"(a1), "r"(a2), "r"(a3), "r"(b0), "r"(b1));
}

__device__ __forceinline__ int edge_at2(const void* eiv, int is64, long idx) {
    return is64 ? (int)((const long long*)eiv)[idx] : ((const int*)eiv)[idx];
}

__device__ __forceinline__ void unpack8h(uint4 u, float* f) {
    float2 a = __half22float2(*(__half2*)&u.x);
    float2 b = __half22float2(*(__half2*)&u.y);
    float2 c = __half22float2(*(__half2*)&u.z);
    float2 d = __half22float2(*(__half2*)&u.w);
    f[0] = a.x; f[1] = a.y; f[2] = b.x; f[3] = b.y;
    f[4] = c.x; f[5] = c.y; f[6] = d.x; f[7] = d.y;
}

// compute BN affine coeffs for channel c from raw stats
__device__ __forceinline__ void bn_coeff(const float* bnsum, const float* bnsq,
                                         const float* gamma, const float* beta,
                                         int c, float& sc, float& sh) {
    float cnt = (float)ROWS;
    float mean = bnsum[c] / cnt;
    float var = bnsq[c] / cnt - mean * mean;
    float inv = rsqrtf(var + 1e-5f);
    sc = gamma[c] * inv;
    sh = beta[c] - mean * sc;
}

// ---------------- graph prep -------------------------------------------------
__global__ void k_zero(const int* __restrict__ ei32) {
    int i = blockIdx.x * blockDim.x + threadIdx.x;
    if (i < NN) g_fill[i] = 0;
    if (i < HH) {
        g_bnsum1[i] = 0.f; g_bnsq1[i] = 0.f;
        g_bnsum2[i] = 0.f; g_bnsq2[i] = 0.f;
    }
    if (blockIdx.x == 0 && threadIdx.x < 32) {
        int lane = threadIdx.x;
        int nz = (ei32[2 * lane + 1] != 0) | (ei32[2 * (lane + 32) + 1] != 0);
        unsigned m = __ballot_sync(0xffffffffu, nz);
        if (lane == 0) g_is64 = (m == 0);
    }
}

__global__ void k_fill_ell(const void* __restrict__ eiv) {
    int is64 = g_is64;
    long e0 = (long)(blockIdx.x * blockDim.x + threadIdx.x) * 4;   // grid covers EE exactly
    int s[4], d[4];
#pragma unroll
    for (int i = 0; i < 4; i++) {
        s[i] = edge_at2(eiv, is64, e0 + i);
        d[i] = edge_at2(eiv, is64, (long)EE + e0 + i);
    }
#pragma unroll
    for (int i = 0; i < 4; i++) {
        int p = atomicAdd(&g_fill[d[i]], 1);
        g_ell[d[i] * PAD + p] = s[i];
    }
}

__global__ void k_dinv() {
    int i = blockIdx.x * blockDim.x + threadIdx.x;
    if (i < NN) g_dinv[i] = rsqrtf((float)(g_fill[i] + 1));   // +1 = self loop
}

// ---------------- W pack (bf16 m16n8k16 fragments, fork stream) ---------------
__global__ void k_prepw(const float* __restrict__ W1, const float* __restrict__ W2,
                        const float* __restrict__ Wc) {
    int blk = blockIdx.x;                 // 0-7 W1, 8-15 W2, 16 Wc
    if (blk < 16) {
        int n = threadIdx.x;
        const float* W = (blk < 8) ? W1 : W2;
        unsigned* fh = (blk < 8) ? g_fW1hi : g_fW2hi;
        unsigned* fl = (blk < 8) ? g_fW1lo : g_fW2lo;
        int kt = blk & 7;
        int nt = n >> 3;
        for (int kk = 0; kk < 16; kk++) {
            int k = kt * 16 + kk;
            float w = W[k * HH + n];
            unsigned short hb = bfbits(w);
            unsigned short lb = bfbits(w - bffloat(hb));
            int r = kk >> 3, t = (kk & 7) >> 1, half = kk & 1;
            int lane = ((n & 7) << 2) | t;
            int idx = ((kt * 16 + nt) * 32 + lane) * 2 + r;
            ((unsigned short*)fh)[idx * 2 + half] = hb;
            ((unsigned short*)fl)[idx * 2 + half] = lb;
        }
    } else {
        int n = threadIdx.x & 15;
        int kt = threadIdx.x >> 4;        // 0..7
        int nt = n >> 3;
        for (int kk = 0; kk < 16; kk++) {
            int k = kt * 16 + kk;
            float w = (n < OO) ? Wc[k * OO + n] : 0.f;
            unsigned short hb = bfbits(w);
            unsigned short lb = bfbits(w - bffloat(hb));
            int r = kk >> 3, t = (kk & 7) >> 1, half = kk & 1;
            int lane = ((n & 7) << 2) | t;
            int idx = ((kt * 2 + nt) * 32 + lane) * 2 + r;
            ((unsigned short*)g_fWchi)[idx * 2 + half] = hb;
            ((unsigned short*)g_fWclo)[idx * 2 + half] = lb;
        }
    }
}

// ---------------- tensor-core GEMM (bf16x3): h16 = fp16(affine(A) @ W) -------
template <int ALAYOUT, int WSEL, bool AFFINE>
__global__ void __launch_bounds__(256) k_gemm_tc(const float* __restrict__ Ain,
                                                 const float* __restrict__ gamma,
                                                 const float* __restrict__ beta) {
    __shared__ __align__(16) unsigned sHi[2][1024];
    __shared__ __align__(16) unsigned sLo[2][1024];
    __shared__ float sSc[HH], sSh[HH];
    const float* A = ALAYOUT ? (const float*)g_buf1 : Ain;
    const unsigned* fH = WSEL ? g_fW2hi : g_fW1hi;
    const unsigned* fL = WSEL ? g_fW2lo : g_fW1lo;

    int tid = threadIdx.x, lane = tid & 31, warp = tid >> 5;
    int b = blockIdx.y;
    int rowBase = blockIdx.x * 128;
    int g = lane >> 2, t = lane & 3;
    int r0 = rowBase + warp * 16 + g;
    int r1 = r0 + 8;
    int rc0 = r0 < NN ? r0 : NN - 1;
    int rc1 = r1 < NN ? r1 : NN - 1;
    long a0b = ALAYOUT ? ((long)rc0 * 2 + b) * HH : ((long)b * NN + rc0) * HH;
    long a1b = ALAYOUT ? ((long)rc1 * 2 + b) * HH : ((long)b * NN + rc1) * HH;

    if (AFFINE && tid < HH) {
        float sc, sh;
        bn_coeff(g_bnsum1, g_bnsq1, gamma, beta, tid, sc, sh);
        sSc[tid] = sc;
        sSh[tid] = sh;
    }

    float acc[16][4];
#pragma unroll
    for (int i = 0; i < 16; i++)
#pragma unroll
        for (int j = 0; j < 4; j++) acc[i][j] = 0.f;

    int ld = tid * 4;
    *(uint4*)&sHi[0][ld] = *(const uint4*)&fH[ld];
    *(uint4*)&sLo[0][ld] = *(const uint4*)&fL[ld];

    // A prefetch for chunk 0: rows r0/r1, cols 2t..2t+1 and 2t+8..2t+9
    float2 pa = __ldg((const float2*)(A + a0b + 2 * t));
    float2 pb = __ldg((const float2*)(A + a1b + 2 * t));
    float2 pc = __ldg((const float2*)(A + a0b + 2 * t + 8));
    float2 pd = __ldg((const float2*)(A + a1b + 2 * t + 8));
    __syncthreads();

    for (int c = 0; c < 8; c++) {
        int cur = c & 1;
        uint4 nh, nl;
        float2 na, nb, nc2, nd;
        if (c < 7) {
            int k1 = (c + 1) * 16;
            na  = __ldg((const float2*)(A + a0b + k1 + 2 * t));
            nb  = __ldg((const float2*)(A + a1b + k1 + 2 * t));
            nc2 = __ldg((const float2*)(A + a0b + k1 + 2 * t + 8));
            nd  = __ldg((const float2*)(A + a1b + k1 + 2 * t + 8));
            nh = *(const uint4*)&fH[(c + 1) * 1024 + ld];
            nl = *(const uint4*)&fL[(c + 1) * 1024 + ld];
        }
        int k0 = c * 16;
        if (AFFINE) {
            float sA = sSc[k0 + 2 * t],     hA = sSh[k0 + 2 * t];
            float sB = sSc[k0 + 2 * t + 1], hB = sSh[k0 + 2 * t + 1];
            float sC = sSc[k0 + 2 * t + 8], hC = sSh[k0 + 2 * t + 8];
            float sD = sSc[k0 + 2 * t + 9], hD = sSh[k0 + 2 * t + 9];
            pa.x = pa.x * sA + hA;  pa.y = pa.y * sB + hB;
            pb.x = pb.x * sA + hA;  pb.y = pb.y * sB + hB;
            pc.x = pc.x * sC + hC;  pc.y = pc.y * sD + hD;
            pd.x = pd.x * sC + hC;  pd.y = pd.y * sD + hD;
        }
        unsigned ah0, al0, ah1, al1, ah2, al2, ah3, al3;
        bfsplit2(pa.x, pa.y, ah0, al0);
        bfsplit2(pb.x, pb.y, ah1, al1);
        bfsplit2(pc.x, pc.y, ah2, al2);
        bfsplit2(pd.x, pd.y, ah3, al3);

#pragma unroll
        for (int nt = 0; nt < 16; nt++) {
            int off = nt * 64 + lane * 2;
            unsigned bh0 = sHi[cur][off], bh1 = sHi[cur][off + 1];
            unsigned bl0 = sLo[cur][off], bl1 = sLo[cur][off + 1];
            mma_bf16(acc[nt], ah0, ah1, ah2, ah3, bh0, bh1);
            mma_bf16(acc[nt], al0, al1, al2, al3, bh0, bh1);
            mma_bf16(acc[nt], ah0, ah1, ah2, ah3, bl0, bl1);
        }
        __syncthreads();
        if (c < 7) {
            int nxt = cur ^ 1;
            *(uint4*)&sHi[nxt][ld] = nh;
            *(uint4*)&sLo[nxt][ld] = nl;
            pa = na; pb = nb; pc = nc2; pd = nd;
        }
        __syncthreads();
    }

#pragma unroll
    for (int nt = 0; nt < 16; nt++) {
        int col = nt * 8 + 2 * t;
        if (r0 < NN)
            *(__half2*)&g_h16[((long)r0 * 2 + b) * HH + col] =
                __floats2half2_rn(acc[nt][0], acc[nt][1]);
        if (r1 < NN)
            *(__half2*)&g_h16[((long)r1 * 2 + b) * HH + col] =
                __floats2half2_rn(acc[nt][2], acc[nt][3]);
    }
}

// ---------------- aggregation (fp16 gather, 8-edge MLP) + BN stats -----------
// one warp per node; lane owns 8 channels of one batch (lane>>4 = batch)
template <int LAYER>
__global__ void __launch_bounds__(256) k_aggbn(const float* __restrict__ bias) {
    float* bnsum = (LAYER == 1) ? g_bnsum1 : g_bnsum2;
    float* bnsq  = (LAYER == 1) ? g_bnsq1 : g_bnsq2;
    __shared__ float ssum[HH], ssq[HH];
    int tid = threadIdx.x;
    if (tid < HH) { ssum[tid] = 0.f; ssq[tid] = 0.f; }
    __syncthreads();

    int node = (blockIdx.x * blockDim.x + tid) >> 5;   // grid*8 == NN exactly
    int lane = tid & 31;
    int bsel = lane >> 4;
    int ch0 = (lane & 15) * 8;
    float din = g_dinv[node];

    const uint4* h16 = (const uint4*)g_h16;   // node row = 32 uint4 (2 batches)
    float f[8], acc[8];
    uint4 u = __ldg(&h16[(long)node * 32 + lane]);
    unpack8h(u, f);
#pragma unroll
    for (int j = 0; j < 8; j++) acc[j] = din * f[j];

    int cnt = g_fill[node];
    const int* row = g_ell + node * PAD;

    int i = 0;
    for (; i + 8 <= cnt; i += 8) {
        int4 sA = __ldg((const int4*)(row + i));
        int4 sB = __ldg((const int4*)(row + i + 4));
        // issue all 8 gathers + 8 weight loads before consuming (MLP)
        uint4 u0 = __ldg(&h16[(long)sA.x * 32 + lane]);
        uint4 u1 = __ldg(&h16[(long)sA.y * 32 + lane]);
        uint4 u2 = __ldg(&h16[(long)sA.z * 32 + lane]);
        uint4 u3 = __ldg(&h16[(long)sA.w * 32 + lane]);
        uint4 u4 = __ldg(&h16[(long)sB.x * 32 + lane]);
        uint4 u5 = __ldg(&h16[(long)sB.y * 32 + lane]);
        uint4 u6 = __ldg(&h16[(long)sB.z * 32 + lane]);
        uint4 u7 = __ldg(&h16[(long)sB.w * 32 + lane]);
        float w0 = __ldg(&g_dinv[sA.x]), w1 = __ldg(&g_dinv[sA.y]);
        float w2 = __ldg(&g_dinv[sA.z]), w3 = __ldg(&g_dinv[sA.w]);
        float w4 = __ldg(&g_dinv[sB.x]), w5 = __ldg(&g_dinv[sB.y]);
        float w6 = __ldg(&g_dinv[sB.z]), w7 = __ldg(&g_dinv[sB.w]);
#define ACC8(U, W)                                                        \
        {                                                                 \
            unpack8h(U, f);                                               \
            _Pragma("unroll")                                             \
            for (int j = 0; j < 8; j++) acc[j] += (W) * f[j];             \
        }
        ACC8(u0, w0); ACC8(u1, w1); ACC8(u2, w2); ACC8(u3, w3);
        ACC8(u4, w4); ACC8(u5, w5); ACC8(u6, w6); ACC8(u7, w7);
    }
    for (; i < cnt; ++i) {
        int s = row[i];
        float w = __ldg(&g_dinv[s]);
        uint4 us = __ldg(&h16[(long)s * 32 + lane]);
        ACC8(us, w);
    }
#undef ACC8

    float bv[8];
    *(float4*)(bv)     = *(const float4*)(bias + ch0);
    *(float4*)(bv + 4) = *(const float4*)(bias + ch0 + 4);
    float rr[8];
#pragma unroll
    for (int j = 0; j < 8; j++) rr[j] = fmaxf(din * acc[j] + bv[j], 0.f);

    float* o = g_buf1 + ((long)node * 2 + bsel) * HH + ch0;
    *(float4*)o       = make_float4(rr[0], rr[1], rr[2], rr[3]);
    *(float4*)(o + 4) = make_float4(rr[4], rr[5], rr[6], rr[7]);

#pragma unroll
    for (int j = 0; j < 8; j++) {
        atomicAdd(&ssum[ch0 + j], rr[j]);
        atomicAdd(&ssq[ch0 + j], rr[j] * rr[j]);
    }
    __syncthreads();
    if (tid < HH) {
        atomicAdd(&bnsum[tid], ssum[tid]);
        atomicAdd(&bnsq[tid], ssq[tid]);
    }
}

// ---------------- tensor-core classifier (bf16x3) ----------------------------
__global__ void __launch_bounds__(256) k_cls_tc(const float* __restrict__ bc,
                                                const float* __restrict__ gamma,
                                                const float* __restrict__ beta,
                                                float* __restrict__ out) {
    __shared__ __align__(16) unsigned sWh[1024], sWl[1024];
    __shared__ float sSc[HH], sSh[HH];
    __shared__ float sbc[16];
    int tid = threadIdx.x, lane = tid & 31, warp = tid >> 5;

    int ld = tid * 4;
    *(uint4*)&sWh[ld] = *(const uint4*)&g_fWchi[ld];
    *(uint4*)&sWl[ld] = *(const uint4*)&g_fWclo[ld];
    if (tid < HH) {
        float sc, sh;
        bn_coeff(g_bnsum2, g_bnsq2, gamma, beta, tid, sc, sh);
        sSc[tid] = sc;
        sSh[tid] = sh;
    }
    if (tid < 16) sbc[tid] = (tid < OO) ? bc[tid] : 0.f;

    int g = lane >> 2, t = lane & 3;
    int r0 = blockIdx.x * 128 + warp * 16 + g;
    int r1 = r0 + 8;
    int rc0 = r0 < ROWS ? r0 : ROWS - 1;
    int rc1 = r1 < ROWS ? r1 : ROWS - 1;
    const float* A = (const float*)g_buf1;
    long a0b = (long)rc0 * HH;
    long a1b = (long)rc1 * HH;

    float acc[2][4];
#pragma unroll
    for (int i = 0; i < 2; i++)
#pragma unroll
        for (int j = 0; j < 4; j++) acc[i][j] = 0.f;

    float2 pa = __ldg((const float2*)(A + a0b + 2 * t));
    float2 pb = __ldg((const float2*)(A + a1b + 2 * t));
    float2 pc = __ldg((const float2*)(A + a0b + 2 * t + 8));
    float2 pd = __ldg((const float2*)(A + a1b + 2 * t + 8));
    __syncthreads();

    for (int c = 0; c < 8; c++) {
        float2 na, nb, nc2, nd;
        if (c < 7) {
            int k1 = (c + 1) * 16;
            na  = __ldg((const float2*)(A + a0b + k1 + 2 * t));
            nb  = __ldg((const float2*)(A + a1b + k1 + 2 * t));
            nc2 = __ldg((const float2*)(A + a0b + k1 + 2 * t + 8));
            nd  = __ldg((const float2*)(A + a1b + k1 + 2 * t + 8));
        }
        int k0 = c * 16;
        float sA = sSc[k0 + 2 * t],     hA = sSh[k0 + 2 * t];
        float sB = sSc[k0 + 2 * t + 1], hB = sSh[k0 + 2 * t + 1];
        float sC = sSc[k0 + 2 * t + 8], hC = sSh[k0 + 2 * t + 8];
        float sD = sSc[k0 + 2 * t + 9], hD = sSh[k0 + 2 * t + 9];
        pa.x = pa.x * sA + hA;  pa.y = pa.y * sB + hB;
        pb.x = pb.x * sA + hA;  pb.y = pb.y * sB + hB;
        pc.x = pc.x * sC + hC;  pc.y = pc.y * sD + hD;
        pd.x = pd.x * sC + hC;  pd.y = pd.y * sD + hD;

        unsigned ah0, al0, ah1, al1, ah2, al2, ah3, al3;
        bfsplit2(pa.x, pa.y, ah0, al0);
        bfsplit2(pb.x, pb.y, ah1, al1);
        bfsplit2(pc.x, pc.y, ah2, al2);
        bfsplit2(pd.x, pd.y, ah3, al3);

#pragma unroll
        for (int nt = 0; nt < 2; nt++) {
            int off = c * 128 + nt * 64 + lane * 2;
            unsigned bh0 = sWh[off], bh1 = sWh[off + 1];
            unsigned bl0 = sWl[off], bl1 = sWl[off + 1];
            mma_bf16(acc[nt], ah0, ah1, ah2, ah3, bh0, bh1);
            mma_bf16(acc[nt], al0, al1, al2, al3, bh0, bh1);
            mma_bf16(acc[nt], ah0, ah1, ah2, ah3, bl0, bl1);
        }
        if (c < 7) { pa = na; pb = nb; pc = nc2; pd = nd; }
    }

#pragma unroll
    for (int nt = 0; nt < 2; nt++) {
        int col = nt * 8 + 2 * t;
        if (col + 1 < OO) {
            if (r0 < ROWS) {
                long o = ((long)(r0 & 1) * NN + (r0 >> 1)) * OO + col;
                out[o]     = acc[nt][0] + sbc[col];
                out[o + 1] = acc[nt][1] + sbc[col + 1];
            }
            if (r1 < ROWS) {
                long o = ((long)(r1 & 1) * NN + (r1 >> 1)) * OO + col;
                out[o]     = acc[nt][2] + sbc[col];
                out[o + 1] = acc[nt][3] + sbc[col + 1];
            }
        }
    }
}

// ---------------- launch -----------------------------------------------------
extern "C" void kernel_launch(void* const* d_in, const int* in_sizes, int n_in,
                              void* d_out, int out_size) {
    const float* x  = (const float*)d_in[0];
    const float* W1 = (const float*)d_in[1];
    const float* b1 = (const float*)d_in[2];
    const float* W2 = (const float*)d_in[3];
    const float* b2 = (const float*)d_in[4];
    const float* g1 = (const float*)d_in[5];
    const float* bt1 = (const float*)d_in[6];
    const float* g2 = (const float*)d_in[7];
    const float* bt2 = (const float*)d_in[8];
    const float* Wc = (const float*)d_in[9];
    const float* bc = (const float*)d_in[10];
    const void* ei = d_in[11];
    float* out = (float*)d_out;

    dim3 ggrid((NN + 127) / 128, BBATCH);   // 157 x 2, 256 threads

    // Fork: W pack + layer-1 GEMM concurrent with graph build.
    cudaStream_t s1;
    cudaStreamCreateWithFlags(&s1, cudaStreamNonBlocking);
    cudaEvent_t ev0, ev1;
    cudaEventCreateWithFlags(&ev0, cudaEventDisableTiming);
    cudaEventCreateWithFlags(&ev1, cudaEventDisableTiming);

    cudaEventRecord(ev0, 0);
    cudaStreamWaitEvent(s1, ev0, 0);
    k_prepw<<<17, 128, 0, s1>>>(W1, W2, Wc);
    k_gemm_tc<0, 0, false><<<ggrid, 256, 0, s1>>>(x, nullptr, nullptr);
    cudaEventRecord(ev1, s1);

    // main stream: graph build (+ BN stat buffer zeroing)
    k_zero<<<(NN + 255) / 256, 256>>>((const int*)ei);
    k_fill_ell<<<EE / 1024, 256>>>(ei);
    k_dinv<<<(NN + 255) / 256, 256>>>();

    // join
    cudaStreamWaitEvent(0, ev1, 0);

    // layer 1 tail (stats -> g_bnsum1/g_bnsq1)
    k_aggbn<1><<<NN / 8, 256>>>(b1);

    // layer 2 (BN1 affine computed per-block from raw stats)
    k_gemm_tc<1, 1, true><<<ggrid, 256>>>(nullptr, g1, bt1);
    k_aggbn<2><<<NN / 8, 256>>>(b2);

    // classifier: tensor-core GEMM, BN2 affine on A-path
    k_cls_tc<<<(ROWS + 127) / 128, 256>>>(bc, g2, bt2, out);
}

// round 16
// speedup vs baseline: 1.2034x; 1.2034x over previous
#include <cuda_runtime.h>
#include <cuda_bf16.h>
#include <cstdint>

#define NN 20000
#define EE 640000
#define BBATCH 2
#define HH 128
#define OO 10
#define PAD 192
#define ROWS (BBATCH * NN)

// ---------------- scratch ----------------------------------------------------
__device__ int   g_fill[NN];          // degree counter / final degree
__device__ int   g_ell[NN * PAD];     // ELL adjacency (src ids)
__device__ float g_dinv[NN];
__device__ int   g_is64;
__device__ __align__(16) float g_buf0[ROWS * HH];
__device__ __align__(16) float g_buf1[ROWS * HH];
__device__ float g_bnsum1[HH], g_bnsq1[HH];   // layer-1 BN stats
__device__ float g_bnsum2[HH], g_bnsq2[HH];   // layer-2 BN stats
// W fragment packs (bf16 hi/lo, m16n8k16): 8 k-chunks x 1024 u32 (16nt x 32 x 2)
__device__ __align__(16) unsigned g_fW1hi[8192];
__device__ __align__(16) unsigned g_fW1lo[8192];
__device__ __align__(16) unsigned g_fW2hi[8192];
__device__ __align__(16) unsigned g_fW2lo[8192];
// Wc fragments: 8 k-chunks x 2 nt x 32 lanes x 2 regs = 1024 u32
__device__ __align__(16) unsigned g_fWchi[1024];
__device__ __align__(16) unsigned g_fWclo[1024];

// ---------------- helpers ----------------------------------------------------
__device__ __forceinline__ unsigned short bfbits(float x) {
    __nv_bfloat16 h = __float2bfloat16_rn(x);
    return *(unsigned short*)&h;
}
__device__ __forceinline__ float bffloat(unsigned short u) {
    __nv_bfloat16 h = *(__nv_bfloat16*)&u;
    return __bfloat162float(h);
}
// split (x,y) into packed bf16x2 hi and lo parts (lower 16 bits = x)
__device__ __forceinline__ void bfsplit2(float x, float y, unsigned& hi, unsigned& lo) {
    unsigned short hx = bfbits(x), hy = bfbits(y);
    unsigned short lx = bfbits(x - bffloat(hx));
    unsigned short ly = bfbits(y - bffloat(hy));
    hi = (unsigned)hx | ((unsigned)hy << 16);
    lo = (unsigned)lx | ((unsigned)ly << 16);
}

__device__ __forceinline__ void mma_bf16(float* d, unsigned a0, unsigned a1,
                                         unsigned a2, unsigned a3,
                                         unsigned b0, unsigned b1) {
    asm volatile(
        "mma.sync.aligned.m16n8k16.row.col.f32.bf16.bf16.f32 "
        "{%0,%1,%2,%3},{%4,%5,%6,%7},{%8,%9},{%0,%1,%2,%3};\n"
        : "+f"(d[0]), "+f"(d[1]), "+f"(d[2]), "+f"(d[3])
        : "r"(a0), "r"(a1), "r"(a2), "r"(a3), "r"(b0), "r"(b1));
}

__device__ __forceinline__ int edge_at2(const void* eiv, int is64, long idx) {
    return is64 ? (int)((const long long*)eiv)[idx] : ((const int*)eiv)[idx];
}

// compute BN affine coeffs for channel c from raw stats
__device__ __forceinline__ void bn_coeff(const float* bnsum, const float* bnsq,
                                         const float* gamma, const float* beta,
                                         int c, float& sc, float& sh) {
    float cnt = (float)ROWS;
    float mean = bnsum[c] / cnt;
    float var = bnsq[c] / cnt - mean * mean;
    float inv = rsqrtf(var + 1e-5f);
    sc = gamma[c] * inv;
    sh = beta[c] - mean * sc;
}

// ---------------- graph prep -------------------------------------------------
__global__ void k_zero(const int* __restrict__ ei32) {
    int i = blockIdx.x * blockDim.x + threadIdx.x;
    if (i < NN) g_fill[i] = 0;
    if (i < HH) {
        g_bnsum1[i] = 0.f; g_bnsq1[i] = 0.f;
        g_bnsum2[i] = 0.f; g_bnsq2[i] = 0.f;
    }
    if (blockIdx.x == 0 && threadIdx.x < 32) {
        int lane = threadIdx.x;
        int nz = (ei32[2 * lane + 1] != 0) | (ei32[2 * (lane + 32) + 1] != 0);
        unsigned m = __ballot_sync(0xffffffffu, nz);
        if (lane == 0) g_is64 = (m == 0);
    }
}

__global__ void k_fill_ell(const void* __restrict__ eiv) {
    int is64 = g_is64;
    long e0 = (long)(blockIdx.x * blockDim.x + threadIdx.x) * 4;   // grid covers EE exactly
    int s[4], d[4];
#pragma unroll
    for (int i = 0; i < 4; i++) {
        s[i] = edge_at2(eiv, is64, e0 + i);
        d[i] = edge_at2(eiv, is64, (long)EE + e0 + i);
    }
#pragma unroll
    for (int i = 0; i < 4; i++) {
        int p = atomicAdd(&g_fill[d[i]], 1);
        g_ell[d[i] * PAD + p] = s[i];
    }
}

__global__ void k_dinv() {
    int i = blockIdx.x * blockDim.x + threadIdx.x;
    if (i < NN) g_dinv[i] = rsqrtf((float)(g_fill[i] + 1));   // +1 = self loop
}

// ---------------- W pack (bf16 m16n8k16 fragments, fork stream) ---------------
__global__ void k_prepw(const float* __restrict__ W1, const float* __restrict__ W2,
                        const float* __restrict__ Wc) {
    int blk = blockIdx.x;                 // 0-7 W1, 8-15 W2, 16 Wc
    if (blk < 16) {
        int n = threadIdx.x;
        const float* W = (blk < 8) ? W1 : W2;
        unsigned* fh = (blk < 8) ? g_fW1hi : g_fW2hi;
        unsigned* fl = (blk < 8) ? g_fW1lo : g_fW2lo;
        int kt = blk & 7;
        int nt = n >> 3;
        for (int kk = 0; kk < 16; kk++) {
            int k = kt * 16 + kk;
            float w = W[k * HH + n];
            unsigned short hb = bfbits(w);
            unsigned short lb = bfbits(w - bffloat(hb));
            int r = kk >> 3, t = (kk & 7) >> 1, half = kk & 1;
            int lane = ((n & 7) << 2) | t;
            int idx = ((kt * 16 + nt) * 32 + lane) * 2 + r;
            ((unsigned short*)fh)[idx * 2 + half] = hb;
            ((unsigned short*)fl)[idx * 2 + half] = lb;
        }
    } else {
        int n = threadIdx.x & 15;
        int kt = threadIdx.x >> 4;        // 0..7
        int nt = n >> 3;
        for (int kk = 0; kk < 16; kk++) {
            int k = kt * 16 + kk;
            float w = (n < OO) ? Wc[k * OO + n] : 0.f;
            unsigned short hb = bfbits(w);
            unsigned short lb = bfbits(w - bffloat(hb));
            int r = kk >> 3, t = (kk & 7) >> 1, half = kk & 1;
            int lane = ((n & 7) << 2) | t;
            int idx = ((kt * 2 + nt) * 32 + lane) * 2 + r;
            ((unsigned short*)g_fWchi)[idx * 2 + half] = hb;
            ((unsigned short*)g_fWclo)[idx * 2 + half] = lb;
        }
    }
}

// ---------------- tensor-core GEMM (bf16x3): C = affine(A) @ Wfrag -----------
// Double-buffered B with ONE barrier per k-chunk (writes to nxt never conflict
// with reads of cur; warps are at most one barrier apart).
template <int ALAYOUT, int WSEL, bool AFFINE>
__global__ void __launch_bounds__(256) k_gemm_tc(const float* __restrict__ Ain,
                                                 const float* __restrict__ gamma,
                                                 const float* __restrict__ beta) {
    __shared__ __align__(16) unsigned sHi[2][1024];
    __shared__ __align__(16) unsigned sLo[2][1024];
    __shared__ float sSc[HH], sSh[HH];
    const float* A = ALAYOUT ? (const float*)g_buf1 : Ain;
    const unsigned* fH = WSEL ? g_fW2hi : g_fW1hi;
    const unsigned* fL = WSEL ? g_fW2lo : g_fW1lo;

    int tid = threadIdx.x, lane = tid & 31, warp = tid >> 5;
    int b = blockIdx.y;
    int rowBase = blockIdx.x * 128;
    int g = lane >> 2, t = lane & 3;
    int r0 = rowBase + warp * 16 + g;
    int r1 = r0 + 8;
    int rc0 = r0 < NN ? r0 : NN - 1;
    int rc1 = r1 < NN ? r1 : NN - 1;
    long a0b = ALAYOUT ? ((long)rc0 * 2 + b) * HH : ((long)b * NN + rc0) * HH;
    long a1b = ALAYOUT ? ((long)rc1 * 2 + b) * HH : ((long)b * NN + rc1) * HH;

    if (AFFINE && tid < HH) {
        float sc, sh;
        bn_coeff(g_bnsum1, g_bnsq1, gamma, beta, tid, sc, sh);
        sSc[tid] = sc;
        sSh[tid] = sh;
    }

    float acc[16][4];
#pragma unroll
    for (int i = 0; i < 16; i++)
#pragma unroll
        for (int j = 0; j < 4; j++) acc[i][j] = 0.f;

    int ld = tid * 4;
    *(uint4*)&sHi[0][ld] = *(const uint4*)&fH[ld];
    *(uint4*)&sLo[0][ld] = *(const uint4*)&fL[ld];

    // A prefetch for chunk 0: rows r0/r1, cols 2t..2t+1 and 2t+8..2t+9
    float2 pa = __ldg((const float2*)(A + a0b + 2 * t));
    float2 pb = __ldg((const float2*)(A + a1b + 2 * t));
    float2 pc = __ldg((const float2*)(A + a0b + 2 * t + 8));
    float2 pd = __ldg((const float2*)(A + a1b + 2 * t + 8));
    __syncthreads();

    for (int c = 0; c < 8; c++) {
        int cur = c & 1;
        uint4 nh, nl;
        float2 na, nb, nc2, nd;
        if (c < 7) {
            int k1 = (c + 1) * 16;
            na  = __ldg((const float2*)(A + a0b + k1 + 2 * t));
            nb  = __ldg((const float2*)(A + a1b + k1 + 2 * t));
            nc2 = __ldg((const float2*)(A + a0b + k1 + 2 * t + 8));
            nd  = __ldg((const float2*)(A + a1b + k1 + 2 * t + 8));
            nh = *(const uint4*)&fH[(c + 1) * 1024 + ld];
            nl = *(const uint4*)&fL[(c + 1) * 1024 + ld];
        }
        int k0 = c * 16;
        if (AFFINE) {
            float sA = sSc[k0 + 2 * t],     hA = sSh[k0 + 2 * t];
            float sB = sSc[k0 + 2 * t + 1], hB = sSh[k0 + 2 * t + 1];
            float sC = sSc[k0 + 2 * t + 8], hC = sSh[k0 + 2 * t + 8];
            float sD = sSc[k0 + 2 * t + 9], hD = sSh[k0 + 2 * t + 9];
            pa.x = pa.x * sA + hA;  pa.y = pa.y * sB + hB;
            pb.x = pb.x * sA + hA;  pb.y = pb.y * sB + hB;
            pc.x = pc.x * sC + hC;  pc.y = pc.y * sD + hD;
            pd.x = pd.x * sC + hC;  pd.y = pd.y * sD + hD;
        }
        unsigned ah0, al0, ah1, al1, ah2, al2, ah3, al3;
        bfsplit2(pa.x, pa.y, ah0, al0);
        bfsplit2(pb.x, pb.y, ah1, al1);
        bfsplit2(pc.x, pc.y, ah2, al2);
        bfsplit2(pd.x, pd.y, ah3, al3);

#pragma unroll
        for (int nt = 0; nt < 16; nt++) {
            int off = nt * 64 + lane * 2;
            unsigned bh0 = sHi[cur][off], bh1 = sHi[cur][off + 1];
            unsigned bl0 = sLo[cur][off], bl1 = sLo[cur][off + 1];
            mma_bf16(acc[nt], ah0, ah1, ah2, ah3, bh0, bh1);
            mma_bf16(acc[nt], al0, al1, al2, al3, bh0, bh1);
            mma_bf16(acc[nt], ah0, ah1, ah2, ah3, bl0, bl1);
        }
        if (c < 7) {
            int nxt = cur ^ 1;            // write other buffer: no conflict with cur readers
            *(uint4*)&sHi[nxt][ld] = nh;
            *(uint4*)&sLo[nxt][ld] = nl;
            pa = na; pb = nb; pc = nc2; pd = nd;
        }
        __syncthreads();                  // single barrier per chunk
    }

#pragma unroll
    for (int nt = 0; nt < 16; nt++) {
        int col = nt * 8 + 2 * t;
        if (r0 < NN)
            *(float2*)&g_buf0[((long)r0 * 2 + b) * HH + col] =
                make_float2(acc[nt][0], acc[nt][1]);
        if (r1 < NN)
            *(float2*)&g_buf0[((long)r1 * 2 + b) * HH + col] =
                make_float2(acc[nt][2], acc[nt][3]);
    }
}

// ---------------- aggregation (fp32, 8-edge MLP) + fused BN stats ------------
template <int LAYER>
__global__ void __launch_bounds__(256) k_aggbn(const float* __restrict__ bias) {
    float* bnsum = (LAYER == 1) ? g_bnsum1 : g_bnsum2;
    float* bnsq  = (LAYER == 1) ? g_bnsq1 : g_bnsq2;
    __shared__ float ssum[HH], ssq[HH];
    int tid = threadIdx.x;
    if (tid < HH) { ssum[tid] = 0.f; ssq[tid] = 0.f; }
    __syncthreads();

    int node = (blockIdx.x * blockDim.x + tid) >> 5;   // grid*8 == NN exactly
    int lane = tid & 31;
    float din = g_dinv[node];

    const float4* h4 = (const float4*)g_buf0;
    long base = (long)node * 64;
    float4 v0 = __ldg(&h4[base + lane]);
    float4 v1 = __ldg(&h4[base + 32 + lane]);
    float4 a0, a1;
    a0.x = din * v0.x; a0.y = din * v0.y; a0.z = din * v0.z; a0.w = din * v0.w;
    a1.x = din * v1.x; a1.y = din * v1.y; a1.z = din * v1.z; a1.w = din * v1.w;

    int cnt = g_fill[node];
    const int* row = g_ell + node * PAD;

#define ACC2(U0, U1, W)                                                    \
    {                                                                      \
        a0.x += (W) * (U0).x; a0.y += (W) * (U0).y;                        \
        a0.z += (W) * (U0).z; a0.w += (W) * (U0).w;                        \
        a1.x += (W) * (U1).x; a1.y += (W) * (U1).y;                        \
        a1.z += (W) * (U1).z; a1.w += (W) * (U1).w;                        \
    }

    int i = 0;
    for (; i + 8 <= cnt; i += 8) {
        int4 sA = __ldg((const int4*)(row + i));
        int4 sB = __ldg((const int4*)(row + i + 4));
        long b0 = (long)sA.x * 64, b1 = (long)sA.y * 64;
        long b2 = (long)sA.z * 64, b3 = (long)sA.w * 64;
        long b4 = (long)sB.x * 64, b5 = (long)sB.y * 64;
        long b6 = (long)sB.z * 64, b7 = (long)sB.w * 64;
        float4 u00 = __ldg(&h4[b0 + lane]),      u01 = __ldg(&h4[b0 + 32 + lane]);
        float4 u10 = __ldg(&h4[b1 + lane]),      u11 = __ldg(&h4[b1 + 32 + lane]);
        float4 u20 = __ldg(&h4[b2 + lane]),      u21 = __ldg(&h4[b2 + 32 + lane]);
        float4 u30 = __ldg(&h4[b3 + lane]),      u31 = __ldg(&h4[b3 + 32 + lane]);
        float4 u40 = __ldg(&h4[b4 + lane]),      u41 = __ldg(&h4[b4 + 32 + lane]);
        float4 u50 = __ldg(&h4[b5 + lane]),      u51 = __ldg(&h4[b5 + 32 + lane]);
        float4 u60 = __ldg(&h4[b6 + lane]),      u61 = __ldg(&h4[b6 + 32 + lane]);
        float4 u70 = __ldg(&h4[b7 + lane]),      u71 = __ldg(&h4[b7 + 32 + lane]);
        float w0 = __ldg(&g_dinv[sA.x]), w1 = __ldg(&g_dinv[sA.y]);
        float w2 = __ldg(&g_dinv[sA.z]), w3 = __ldg(&g_dinv[sA.w]);
        float w4 = __ldg(&g_dinv[sB.x]), w5 = __ldg(&g_dinv[sB.y]);
        float w6 = __ldg(&g_dinv[sB.z]), w7 = __ldg(&g_dinv[sB.w]);
        ACC2(u00, u01, w0); ACC2(u10, u11, w1);
        ACC2(u20, u21, w2); ACC2(u30, u31, w3);
        ACC2(u40, u41, w4); ACC2(u50, u51, w5);
        ACC2(u60, u61, w6); ACC2(u70, u71, w7);
    }
    for (; i < cnt; ++i) {
        int s = row[i];
        float w = __ldg(&g_dinv[s]);
        long sb = (long)s * 64;
        float4 u0 = __ldg(&h4[sb + lane]);
        float4 u1 = __ldg(&h4[sb + 32 + lane]);
        ACC2(u0, u1, w);
    }
#undef ACC2

    float4 bv = *(const float4*)(bias + lane * 4);
    float4 rr0, rr1;
    rr0.x = fmaxf(din * a0.x + bv.x, 0.f);
    rr0.y = fmaxf(din * a0.y + bv.y, 0.f);
    rr0.z = fmaxf(din * a0.z + bv.z, 0.f);
    rr0.w = fmaxf(din * a0.w + bv.w, 0.f);
    rr1.x = fmaxf(din * a1.x + bv.x, 0.f);
    rr1.y = fmaxf(din * a1.y + bv.y, 0.f);
    rr1.z = fmaxf(din * a1.z + bv.z, 0.f);
    rr1.w = fmaxf(din * a1.w + bv.w, 0.f);

    float4* o4 = (float4*)g_buf1;
    o4[base + lane] = rr0;
    o4[base + 32 + lane] = rr1;

    int ch = lane * 4;
    atomicAdd(&ssum[ch + 0], rr0.x + rr1.x);
    atomicAdd(&ssum[ch + 1], rr0.y + rr1.y);
    atomicAdd(&ssum[ch + 2], rr0.z + rr1.z);
    atomicAdd(&ssum[ch + 3], rr0.w + rr1.w);
    atomicAdd(&ssq[ch + 0], rr0.x * rr0.x + rr1.x * rr1.x);
    atomicAdd(&ssq[ch + 1], rr0.y * rr0.y + rr1.y * rr1.y);
    atomicAdd(&ssq[ch + 2], rr0.z * rr0.z + rr1.z * rr1.z);
    atomicAdd(&ssq[ch + 3], rr0.w * rr0.w + rr1.w * rr1.w);
    __syncthreads();
    if (tid < HH) {
        atomicAdd(&bnsum[tid], ssum[tid]);
        atomicAdd(&bnsq[tid], ssq[tid]);
    }
}

// ---------------- tensor-core classifier (bf16x3) ----------------------------
__global__ void __launch_bounds__(256) k_cls_tc(const float* __restrict__ bc,
                                                const float* __restrict__ gamma,
                                                const float* __restrict__ beta,
                                                float* __restrict__ out) {
    __shared__ __align__(16) unsigned sWh[1024], sWl[1024];
    __shared__ float sSc[HH], sSh[HH];
    __shared__ float sbc[16];
    int tid = threadIdx.x, lane = tid & 31, warp = tid >> 5;

    int ld = tid * 4;
    *(uint4*)&sWh[ld] = *(const uint4*)&g_fWchi[ld];
    *(uint4*)&sWl[ld] = *(const uint4*)&g_fWclo[ld];
    if (tid < HH) {
        float sc, sh;
        bn_coeff(g_bnsum2, g_bnsq2, gamma, beta, tid, sc, sh);
        sSc[tid] = sc;
        sSh[tid] = sh;
    }
    if (tid < 16) sbc[tid] = (tid < OO) ? bc[tid] : 0.f;

    int g = lane >> 2, t = lane & 3;
    int r0 = blockIdx.x * 128 + warp * 16 + g;
    int r1 = r0 + 8;
    int rc0 = r0 < ROWS ? r0 : ROWS - 1;
    int rc1 = r1 < ROWS ? r1 : ROWS - 1;
    const float* A = (const float*)g_buf1;
    long a0b = (long)rc0 * HH;
    long a1b = (long)rc1 * HH;

    float acc[2][4];
#pragma unroll
    for (int i = 0; i < 2; i++)
#pragma unroll
        for (int j = 0; j < 4; j++) acc[i][j] = 0.f;

    float2 pa = __ldg((const float2*)(A + a0b + 2 * t));
    float2 pb = __ldg((const float2*)(A + a1b + 2 * t));
    float2 pc = __ldg((const float2*)(A + a0b + 2 * t + 8));
    float2 pd = __ldg((const float2*)(A + a1b + 2 * t + 8));
    __syncthreads();

    for (int c = 0; c < 8; c++) {
        float2 na, nb, nc2, nd;
        if (c < 7) {
            int k1 = (c + 1) * 16;
            na  = __ldg((const float2*)(A + a0b + k1 + 2 * t));
            nb  = __ldg((const float2*)(A + a1b + k1 + 2 * t));
            nc2 = __ldg((const float2*)(A + a0b + k1 + 2 * t + 8));
            nd  = __ldg((const float2*)(A + a1b + k1 + 2 * t + 8));
        }
        int k0 = c * 16;
        float sA = sSc[k0 + 2 * t],     hA = sSh[k0 + 2 * t];
        float sB = sSc[k0 + 2 * t + 1], hB = sSh[k0 + 2 * t + 1];
        float sC = sSc[k0 + 2 * t + 8], hC = sSh[k0 + 2 * t + 8];
        float sD = sSc[k0 + 2 * t + 9], hD = sSh[k0 + 2 * t + 9];
        pa.x = pa.x * sA + hA;  pa.y = pa.y * sB + hB;
        pb.x = pb.x * sA + hA;  pb.y = pb.y * sB + hB;
        pc.x = pc.x * sC + hC;  pc.y = pc.y * sD + hD;
        pd.x = pd.x * sC + hC;  pd.y = pd.y * sD + hD;

        unsigned ah0, al0, ah1, al1, ah2, al2, ah3, al3;
        bfsplit2(pa.x, pa.y, ah0, al0);
        bfsplit2(pb.x, pb.y, ah1, al1);
        bfsplit2(pc.x, pc.y, ah2, al2);
        bfsplit2(pd.x, pd.y, ah3, al3);

#pragma unroll
        for (int nt = 0; nt < 2; nt++) {
            int off = c * 128 + nt * 64 + lane * 2;
            unsigned bh0 = sWh[off], bh1 = sWh[off + 1];
            unsigned bl0 = sWl[off], bl1 = sWl[off + 1];
            mma_bf16(acc[nt], ah0, ah1, ah2, ah3, bh0, bh1);
            mma_bf16(acc[nt], al0, al1, al2, al3, bh0, bh1);
            mma_bf16(acc[nt], ah0, ah1, ah2, ah3, bl0, bl1);
        }
        if (c < 7) { pa = na; pb = nb; pc = nc2; pd = nd; }
    }

#pragma unroll
    for (int nt = 0; nt < 2; nt++) {
        int col = nt * 8 + 2 * t;
        if (col + 1 < OO) {
            if (r0 < ROWS) {
                long o = ((long)(r0 & 1) * NN + (r0 >> 1)) * OO + col;
                out[o]     = acc[nt][0] + sbc[col];
                out[o + 1] = acc[nt][1] + sbc[col + 1];
            }
            if (r1 < ROWS) {
                long o = ((long)(r1 & 1) * NN + (r1 >> 1)) * OO + col;
                out[o]     = acc[nt][2] + sbc[col];
                out[o + 1] = acc[nt][3] + sbc[col + 1];
            }
        }
    }
}

// ---------------- launch -----------------------------------------------------
extern "C" void kernel_launch(void* const* d_in, const int* in_sizes, int n_in,
                              void* d_out, int out_size) {
    const float* x  = (const float*)d_in[0];
    const float* W1 = (const float*)d_in[1];
    const float* b1 = (const float*)d_in[2];
    const float* W2 = (const float*)d_in[3];
    const float* b2 = (const float*)d_in[4];
    const float* g1 = (const float*)d_in[5];
    const float* bt1 = (const float*)d_in[6];
    const float* g2 = (const float*)d_in[7];
    const float* bt2 = (const float*)d_in[8];
    const float* Wc = (const float*)d_in[9];
    const float* bc = (const float*)d_in[10];
    const void* ei = d_in[11];
    float* out = (float*)d_out;

    dim3 ggrid((NN + 127) / 128, BBATCH);   // 157 x 2, 256 threads

    // Fork: W pack + layer-1 GEMM concurrent with graph build.
    cudaStream_t s1;
    cudaStreamCreateWithFlags(&s1, cudaStreamNonBlocking);
    cudaEvent_t ev0, ev1;
    cudaEventCreateWithFlags(&ev0, cudaEventDisableTiming);
    cudaEventCreateWithFlags(&ev1, cudaEventDisableTiming);

    cudaEventRecord(ev0, 0);
    cudaStreamWaitEvent(s1, ev0, 0);
    k_prepw<<<17, 128, 0, s1>>>(W1, W2, Wc);
    k_gemm_tc<0, 0, false><<<ggrid, 256, 0, s1>>>(x, nullptr, nullptr);
    cudaEventRecord(ev1, s1);

    // main stream: graph build (+ BN stat buffer zeroing)
    k_zero<<<(NN + 255) / 256, 256>>>((const int*)ei);
    k_fill_ell<<<EE / 1024, 256>>>(ei);
    k_dinv<<<(NN + 255) / 256, 256>>>();

    // join
    cudaStreamWaitEvent(0, ev1, 0);

    // layer 1 tail (stats -> g_bnsum1/g_bnsq1)
    k_aggbn<1><<<NN / 8, 256>>>(b1);

    // layer 2 (BN1 affine computed per-block from raw stats)
    k_gemm_tc<1, 1, true><<<ggrid, 256>>>(nullptr, g1, bt1);
    k_aggbn<2><<<NN / 8, 256>>>(b2);

    // classifier: tensor-core GEMM, BN2 affine on A-path
    k_cls_tc<<<(ROWS + 127) / 128, 256>>>(bc, g2, bt2, out);
}